// round 13
// baseline (speedup 1.0000x reference)
#include <cuda_runtime.h>
#include <cuda_bf16.h>
#include <math_constants.h>
#include <cstdint>

// Problem constants
#define BATCH 8
#define TSEQ  2048
#define NHEAD 6
#define HDIM  64
#define CDIM  (NHEAD * HDIM)      // 384
#define C3    (3 * CDIM)          // 1152
#define MROWS (BATCH * TSEQ)      // 16384

#define SCALE_LOG2E 0.18033688011112042f   // (1/8) * log2(e), folded into q

// Scratch (device globals; no runtime allocation allowed)
__device__ float g_q[BATCH * NHEAD * TSEQ * HDIM];   // [B,H,T,D] tf32, pre-scaled
__device__ float g_k[BATCH * NHEAD * TSEQ * HDIM];
__device__ float g_v[BATCH * NHEAD * TSEQ * HDIM];
__device__ float g_att[MROWS * CDIM];                // [B,T,C] tf32-rounded
__device__ float g_xr[MROWS * CDIM];                 // x tf32-rounded
__device__ float g_wqkvT[C3 * CDIM];                 // w_qkv^T [1152][384], tf32
__device__ float g_wpT[CDIM * CDIM];                 // w_proj^T [384][384], tf32

// ---------------------------------------------------------------------------
// Helpers
// ---------------------------------------------------------------------------
__device__ __forceinline__ unsigned f2tf32(float f) {
    unsigned u;
    asm("cvt.rna.tf32.f32 %0, %1;" : "=r"(u) : "f"(f));
    return u;
}
__device__ __forceinline__ float rtf(float f) { return __uint_as_float(f2tf32(f)); }
__device__ __forceinline__ float fast_exp2(float x) {
    float y;
    asm("ex2.approx.f32 %0, %1;" : "=f"(y) : "f"(x));
    return y;
}
__device__ __forceinline__ void mma_tf32(float* d, const unsigned* a, unsigned b0, unsigned b1) {
    asm volatile(
        "mma.sync.aligned.m16n8k8.row.col.f32.tf32.tf32.f32 "
        "{%0,%1,%2,%3},{%4,%5,%6,%7},{%8,%9},{%0,%1,%2,%3};"
        : "+f"(d[0]), "+f"(d[1]), "+f"(d[2]), "+f"(d[3])
        : "r"(a[0]), "r"(a[1]), "r"(a[2]), "r"(a[3]), "r"(b0), "r"(b1));
}
__device__ __forceinline__ unsigned smaddr(const void* p) {
    return (unsigned)__cvta_generic_to_shared(p);
}
__device__ __forceinline__ void cp16(unsigned dst, const void* src) {
    asm volatile("cp.async.cg.shared.global [%0], [%1], 16;" :: "r"(dst), "l"(src));
}
#define SWZ128(bo) ((bo) ^ (((bo) >> 3) & 0x70))
// byte-offset swizzle for 256-byte-pitch tiles (matches staging: bits[4:6] ^= row&7)
__device__ __forceinline__ int swb(int row, int col) {
    return row * 256 + ((((col >> 2) ^ (row & 7)) << 4) | ((col & 3) << 2));
}

// ---------------------------------------------------------------------------
// Pre-round x to tf32 (elementwise, vectorized)
// ---------------------------------------------------------------------------
__global__ __launch_bounds__(256) void preround_kernel(const float* __restrict__ x)
{
    float4* dst = (float4*)g_xr;
    const float4* src = (const float4*)x;
    int i = blockIdx.x * 256 + threadIdx.x;
    float4 v = src[i];
    dst[i] = make_float4(rtf(v.x), rtf(v.y), rtf(v.z), rtf(v.w));
}

// ---------------------------------------------------------------------------
// Weight transpose + tf32 round: dst[n][k] = round(src[k][n])
// ---------------------------------------------------------------------------
template<bool PROJ>
__global__ void transpose_kernel(const float* __restrict__ src, int C)
{
    float* dst = PROJ ? (float*)g_wpT : (float*)g_wqkvT;
    __shared__ float t[32][33];
    const int bx = blockIdx.x * 32;
    const int by = blockIdx.y * 32;
    const int x = threadIdx.x, y = threadIdx.y;
    #pragma unroll
    for (int j = 0; j < 32; j += 8)
        t[y + j][x] = src[(size_t)(by + y + j) * C + bx + x];
    __syncthreads();
    #pragma unroll
    for (int j = 0; j < 32; j += 8)
        dst[(size_t)(bx + y + j) * CDIM + by + x] = rtf(t[x][y + j]);
}

// ---------------------------------------------------------------------------
// TF32 GEMM, cp.async double-buffered BK=32 chunks (round-10, unchanged)
// ---------------------------------------------------------------------------
#define GEMM_SMEM_BYTES 65536   // A 2x16KB + B 2x16KB

template<int NC, bool PROJ>
__global__ __launch_bounds__(256, 2) void gemm_cp_kernel(
    const float* __restrict__ bias, float* __restrict__ out)
{
    extern __shared__ float smf[];
    float* Abuf = smf;             // [2][4096]
    float* Bbuf = smf + 8192;      // [2][4096]

    const float* A  = PROJ ? (const float*)g_att : (const float*)g_xr;
    const float* BT = PROJ ? (const float*)g_wpT : (const float*)g_wqkvT;

    const int tid  = threadIdx.x;
    const int lane = tid & 31, warp = tid >> 5;
    const int wm = warp >> 1, wn = warp & 1;
    const int gid = lane >> 2, tig = lane & 3;
    const int bm = blockIdx.y * 128, bn = blockIdx.x * 128;

#define GSTAGE(c, buf) do { \
        float* Ad = Abuf + (buf) * 4096; \
        float* Bd = Bbuf + (buf) * 4096; \
        _Pragma("unroll") \
        for (int i = 0; i < 4; i++) { \
            const int idx = i * 256 + tid; \
            const int row = idx >> 3, c4 = idx & 7; \
            const unsigned so = SWZ128((unsigned)(row * 128 + c4 * 16)); \
            cp16(smaddr((char*)Ad + so), A  + (size_t)(bm + row) * CDIM + (c) * 32 + c4 * 4); \
            cp16(smaddr((char*)Bd + so), BT + (size_t)(bn + row) * CDIM + (c) * 32 + c4 * 4); \
        } \
        asm volatile("cp.async.commit_group;"); \
    } while (0)

    float acc[2][8][4];
    #pragma unroll
    for (int mi = 0; mi < 2; mi++)
        #pragma unroll
        for (int ni = 0; ni < 8; ni++)
            #pragma unroll
            for (int c = 0; c < 4; c++) acc[mi][ni][c] = 0.f;

    GSTAGE(0, 0);

    #pragma unroll 1
    for (int c = 0; c < 12; c++) {
        const int cur = c & 1;
        asm volatile("cp.async.wait_group 0;");
        __syncthreads();
        if (c < 11) GSTAGE(c + 1, cur ^ 1);

        const char* Ab = (const char*)(Abuf + cur * 4096);
        const char* Bb = (const char*)(Bbuf + cur * 4096);

        #pragma unroll
        for (int ks = 0; ks < 4; ks++) {
            const int k0 = ks * 8 + tig;
            const int k1 = k0 + 4;

            unsigned a[2][4];
            #pragma unroll
            for (int mi = 0; mi < 2; mi++) {
                const int m = wm * 32 + mi * 16 + gid;
                a[mi][0] = *(const unsigned*)(Ab + SWZ128((unsigned)(m * 128 + k0 * 4)));
                a[mi][1] = *(const unsigned*)(Ab + SWZ128((unsigned)((m + 8) * 128 + k0 * 4)));
                a[mi][2] = *(const unsigned*)(Ab + SWZ128((unsigned)(m * 128 + k1 * 4)));
                a[mi][3] = *(const unsigned*)(Ab + SWZ128((unsigned)((m + 8) * 128 + k1 * 4)));
            }
            #pragma unroll
            for (int ni = 0; ni < 8; ni++) {
                const int n = wn * 64 + ni * 8 + gid;
                unsigned b0 = *(const unsigned*)(Bb + SWZ128((unsigned)(n * 128 + k0 * 4)));
                unsigned b1 = *(const unsigned*)(Bb + SWZ128((unsigned)(n * 128 + k1 * 4)));
                mma_tf32(acc[0][ni], a[0], b0, b1);
                mma_tf32(acc[1][ni], a[1], b0, b1);
            }
        }
        __syncthreads();
    }
#undef GSTAGE

    #pragma unroll
    for (int mi = 0; mi < 2; mi++) {
        const int r0 = bm + wm * 32 + mi * 16 + gid;
        const int r1 = r0 + 8;
        #pragma unroll
        for (int ni = 0; ni < 8; ni++) {
            if (PROJ) {
                const int c = bn + wn * 64 + ni * 8 + tig * 2;
                float bx = bias[c], by = bias[c + 1];
                *(float2*)(out + (size_t)r0 * CDIM + c) =
                    make_float2(acc[mi][ni][0] + bx, acc[mi][ni][1] + by);
                *(float2*)(out + (size_t)r1 * CDIM + c) =
                    make_float2(acc[mi][ni][2] + bx, acc[mi][ni][3] + by);
            } else {
                const int which = bn / CDIM;
                const int cloc  = (bn % CDIM) + wn * 64 + ni * 8 + tig * 2;
                const int h = cloc >> 6, dd = cloc & 63;
                float* dst = (which == 0) ? g_q : (which == 1) ? g_k : g_v;
                const float sc = (which == 0) ? SCALE_LOG2E : 1.0f;
                const int b0r = r0 >> 11, t0 = r0 & 2047;
                const int b1r = r1 >> 11, t1 = r1 & 2047;
                float2 v0 = make_float2(rtf(acc[mi][ni][0] * sc), rtf(acc[mi][ni][1] * sc));
                float2 v1 = make_float2(rtf(acc[mi][ni][2] * sc), rtf(acc[mi][ni][3] * sc));
                *(float2*)(dst + (((size_t)(b0r * NHEAD + h) * TSEQ + t0) << 6) + dd) = v0;
                *(float2*)(dst + (((size_t)(b1r * NHEAD + h) * TSEQ + t1) << 6) + dd) = v1;
            }
        }
    }
}

// ---------------------------------------------------------------------------
// Causal flash attention v3 (round-12 design, read-swizzle FIXED):
//  - NO P smem: accumulator->A-fragment via quad shuffles
//  - S and PV fused per n-chunk
//  - S-MMA split into two 4-deep chains
//  - Q fragments loaded directly from gmem
//  - smem 64KB -> 3 CTAs/SM
//  - fragment reads use swb() (256B-pitch swizzle matching the staging)
// ---------------------------------------------------------------------------
#define FLASH_SMEM_BYTES 65536

__global__ __launch_bounds__(256, 3) void flash_attn_kernel()
{
    extern __shared__ float smf[];
    float* Kbuf = smf;             // [2][4096]
    float* Vbuf = smf + 8192;      // [2][4096]

    const int bh   = blockIdx.y;
    const int qb   = 15 - blockIdx.x;      // heavy q-blocks first
    const int tid  = threadIdx.x;
    const int lane = tid & 31;
    const int warp = tid >> 5;
    const int gid  = lane >> 2;
    const int tig  = lane & 3;

    const float* __restrict__ Qb = g_q + (size_t)bh * TSEQ * HDIM;
    const float* __restrict__ Kb = g_k + (size_t)bh * TSEQ * HDIM;
    const float* __restrict__ Vb = g_v + (size_t)bh * TSEQ * HDIM;

    const int qrow0 = warp * 16 + gid;
    const int qg0   = qb * 128 + qrow0;
    const int qg1   = qg0 + 8;

    // ---- preload KV tile 0 into buffer 0 ----
    {
        const float4* Kg = (const float4*)Kb;
        const float4* Vg = (const float4*)Vb;
        #pragma unroll
        for (int i = 0; i < 4; i++) {
            int idx = i * 256 + tid;
            int row = idx >> 4, c4 = idx & 15;
            int s4 = row * 16 + (c4 ^ (row & 7));
            cp16(smaddr(Kbuf + s4 * 4), Kg + idx);
            cp16(smaddr(Vbuf + s4 * 4), Vg + idx);
        }
        asm volatile("cp.async.commit_group;");
    }

    // ---- Q fragments straight from gmem (pre-rounded, pre-scaled) ----
    unsigned qa[8][4];
    {
        const float* q0 = Qb + (size_t)qg0 * HDIM;
        const float* q1 = Qb + (size_t)qg1 * HDIM;
        #pragma unroll
        for (int kc = 0; kc < 8; kc++) {
            int col = kc * 8 + tig;
            qa[kc][0] = __float_as_uint(q0[col]);
            qa[kc][1] = __float_as_uint(q1[col]);
            qa[kc][2] = __float_as_uint(q0[col + 4]);
            qa[kc][3] = __float_as_uint(q1[col + 4]);
        }
    }

    const int jtmax  = 2 * qb + 1;
    const int mydiag = 2 * qb + (warp >> 2);
    const int sl0 = (lane & 28) | (tig >> 1);   // source lane for cols {t}
    const int sl2 = sl0 + 2;                    // source lane for cols {t+4}
    const bool odd = (tig & 1);

    float o[8][4];
    #pragma unroll
    for (int n = 0; n < 8; n++)
        #pragma unroll
        for (int c = 0; c < 4; c++) o[n][c] = 0.f;
    float l0 = 0.f, l1 = 0.f;

    #pragma unroll 1
    for (int jt = 0; jt <= jtmax; jt++) {
        const int cur = jt & 1;

        asm volatile("cp.async.wait_group 0;");
        __syncthreads();

        if (jt < jtmax) {
            const float4* Kg = (const float4*)(Kb + (size_t)(jt + 1) * 64 * HDIM);
            const float4* Vg = (const float4*)(Vb + (size_t)(jt + 1) * 64 * HDIM);
            float* Kd = Kbuf + (cur ^ 1) * 4096;
            float* Vd = Vbuf + (cur ^ 1) * 4096;
            #pragma unroll
            for (int i = 0; i < 4; i++) {
                int idx = i * 256 + tid;
                int row = idx >> 4, c4 = idx & 15;
                int s4 = row * 16 + (c4 ^ (row & 7));
                cp16(smaddr(Kd + s4 * 4), Kg + idx);
                cp16(smaddr(Vd + s4 * 4), Vg + idx);
            }
            asm volatile("cp.async.commit_group;");
        }

        if (jt <= mydiag) {
            const char* Ks = (const char*)(Kbuf + cur * 4096);
            const char* Vs = (const char*)(Vbuf + cur * 4096);
            const bool diag = (jt == mydiag);
            const int jbase = jt * 64;

            #pragma unroll
            for (int n = 0; n < 8; n++) {
                // ---- S(n) = Q K^T, two independent 4-deep MMA chains ----
                float sa[4] = {0.f, 0.f, 0.f, 0.f};
                float sb[4] = {0.f, 0.f, 0.f, 0.f};
                const int krow = n * 8 + gid;
                #pragma unroll
                for (int kc = 0; kc < 8; kc += 2) {
                    unsigned b0 = *(const unsigned*)(Ks + swb(krow, kc * 8 + tig));
                    unsigned b1 = *(const unsigned*)(Ks + swb(krow, kc * 8 + tig + 4));
                    mma_tf32(sa, qa[kc], b0, b1);
                    unsigned c0 = *(const unsigned*)(Ks + swb(krow, kc * 8 + 8 + tig));
                    unsigned c1 = *(const unsigned*)(Ks + swb(krow, kc * 8 + 12 + tig));
                    mma_tf32(sb, qa[kc + 1], c0, c1);
                }
                float s0 = sa[0] + sb[0];
                float s1 = sa[1] + sb[1];
                float s2 = sa[2] + sb[2];
                float s3 = sa[3] + sb[3];

                if (diag) {
                    int j0 = jbase + n * 8 + 2 * tig;
                    if (j0 > qg0)     s0 = -1e30f;
                    if (j0 + 1 > qg0) s1 = -1e30f;
                    if (j0 > qg1)     s2 = -1e30f;
                    if (j0 + 1 > qg1) s3 = -1e30f;
                }

                float p0 = fast_exp2(fminf(s0, 30.f));
                float p1 = fast_exp2(fminf(s1, 30.f));
                float p2 = fast_exp2(fminf(s2, 30.f));
                float p3 = fast_exp2(fminf(s3, 30.f));
                l0 += p0 + p1;
                l1 += p2 + p3;

                // ---- accumulator layout -> A-fragment layout (quad shuffles) ----
                float u0 = __shfl_sync(0xffffffffu, p0, sl0);
                float u1 = __shfl_sync(0xffffffffu, p1, sl0);
                float v0 = __shfl_sync(0xffffffffu, p0, sl2);
                float v1 = __shfl_sync(0xffffffffu, p1, sl2);
                float w0 = __shfl_sync(0xffffffffu, p2, sl0);
                float w1 = __shfl_sync(0xffffffffu, p3, sl0);
                float x0 = __shfl_sync(0xffffffffu, p2, sl2);
                float x1 = __shfl_sync(0xffffffffu, p3, sl2);
                unsigned pa[4];
                pa[0] = f2tf32(odd ? u1 : u0);   // P[gid][n*8+tig]
                pa[1] = f2tf32(odd ? w1 : w0);   // P[gid+8][n*8+tig]
                pa[2] = f2tf32(odd ? v1 : v0);   // P[gid][n*8+tig+4]
                pa[3] = f2tf32(odd ? x1 : x0);   // P[gid+8][n*8+tig+4]

                // ---- O += P(:, n-chunk) V(n-chunk, :) ----
                const int vr0 = n * 8 + tig;
                const int vr1 = vr0 + 4;
                #pragma unroll
                for (int dn = 0; dn < 8; dn++) {
                    unsigned b0 = *(const unsigned*)(Vs + swb(vr0, dn * 8 + gid));
                    unsigned b1 = *(const unsigned*)(Vs + swb(vr1, dn * 8 + gid));
                    mma_tf32(o[dn], pa, b0, b1);
                }
            }
        }
    }

    // end-of-kernel quad reduction of row sums
    l0 += __shfl_xor_sync(0xffffffffu, l0, 1);
    l0 += __shfl_xor_sync(0xffffffffu, l0, 2);
    l1 += __shfl_xor_sync(0xffffffffu, l1, 1);
    l1 += __shfl_xor_sync(0xffffffffu, l1, 2);

    const float inv0 = 1.f / l0;
    const float inv1 = 1.f / l1;
    const int b = bh / NHEAD, h = bh % NHEAD;
    float* base0 = g_att + (size_t)(b * TSEQ + qg0) * CDIM + h * HDIM;
    float* base1 = g_att + (size_t)(b * TSEQ + qg1) * CDIM + h * HDIM;
    #pragma unroll
    for (int dn = 0; dn < 8; dn++) {
        int col = dn * 8 + 2 * tig;
        *(float2*)(base0 + col) = make_float2(rtf(o[dn][0] * inv0), rtf(o[dn][1] * inv0));
        *(float2*)(base1 + col) = make_float2(rtf(o[dn][2] * inv1), rtf(o[dn][3] * inv1));
    }
}

// ---------------------------------------------------------------------------
extern "C" void kernel_launch(void* const* d_in, const int* in_sizes, int n_in,
                              void* d_out, int out_size)
{
    const float* x      = (const float*)d_in[0];   // [8,2048,384]
    const float* w_qkv  = (const float*)d_in[1];   // [384,1152]
    const float* w_proj = (const float*)d_in[2];   // [384,384]
    const float* b_proj = (const float*)d_in[3];   // [384]
    float* out = (float*)d_out;                    // [8,2048,384]

    cudaFuncSetAttribute(gemm_cp_kernel<C3, false>,
                         cudaFuncAttributeMaxDynamicSharedMemorySize, GEMM_SMEM_BYTES);
    cudaFuncSetAttribute(gemm_cp_kernel<CDIM, true>,
                         cudaFuncAttributeMaxDynamicSharedMemorySize, GEMM_SMEM_BYTES);
    cudaFuncSetAttribute(flash_attn_kernel,
                         cudaFuncAttributeMaxDynamicSharedMemorySize, FLASH_SMEM_BYTES);

    {
        preround_kernel<<<MROWS * CDIM / 4 / 256, 256>>>(x);
        dim3 blk(32, 8);
        transpose_kernel<false><<<dim3(C3 / 32, CDIM / 32), blk>>>(w_qkv, C3);
        transpose_kernel<true><<<dim3(CDIM / 32, CDIM / 32), blk>>>(w_proj, CDIM);
    }
    {
        dim3 grid(C3 / 128, MROWS / 128);          // (9, 128)
        gemm_cp_kernel<C3, false><<<grid, 256, GEMM_SMEM_BYTES>>>(nullptr, nullptr);
    }
    {
        dim3 grid(TSEQ / 128, BATCH * NHEAD);      // (16, 48)
        flash_attn_kernel<<<grid, 256, FLASH_SMEM_BYTES>>>();
    }
    {
        dim3 grid(CDIM / 128, MROWS / 128);        // (3, 128)
        gemm_cp_kernel<CDIM, true><<<grid, 256, GEMM_SMEM_BYTES>>>(b_proj, out);
    }
}

// round 14
// speedup vs baseline: 1.9238x; 1.9238x over previous
#include <cuda_runtime.h>
#include <cuda_bf16.h>
#include <math_constants.h>
#include <cstdint>

// Problem constants
#define BATCH 8
#define TSEQ  2048
#define NHEAD 6
#define HDIM  64
#define CDIM  (NHEAD * HDIM)      // 384
#define C3    (3 * CDIM)          // 1152
#define MROWS (BATCH * TSEQ)      // 16384

#define SCALE_LOG2E 0.18033688011112042f   // (1/8) * log2(e), folded into q

// Scratch (device globals; no runtime allocation allowed)
__device__ float g_q[BATCH * NHEAD * TSEQ * HDIM];   // [B,H,T,D] tf32, pre-scaled
__device__ float g_k[BATCH * NHEAD * TSEQ * HDIM];
__device__ float g_v[BATCH * NHEAD * TSEQ * HDIM];
__device__ float g_att[MROWS * CDIM];                // [B,T,C] fp32

// ---------------------------------------------------------------------------
// Helpers
// ---------------------------------------------------------------------------
__device__ __forceinline__ unsigned f2tf32(float f) {
    unsigned u;
    asm("cvt.rna.tf32.f32 %0, %1;" : "=r"(u) : "f"(f));
    return u;
}
__device__ __forceinline__ float fast_exp2(float x) {
    float y;
    asm("ex2.approx.f32 %0, %1;" : "=f"(y) : "f"(x));
    return y;
}
__device__ __forceinline__ void mma_tf32(float* d, const unsigned* a, unsigned b0, unsigned b1) {
    asm volatile(
        "mma.sync.aligned.m16n8k8.row.col.f32.tf32.tf32.f32 "
        "{%0,%1,%2,%3},{%4,%5,%6,%7},{%8,%9},{%0,%1,%2,%3};"
        : "+f"(d[0]), "+f"(d[1]), "+f"(d[2]), "+f"(d[3])
        : "r"(a[0]), "r"(a[1]), "r"(a[2]), "r"(a[3]), "r"(b0), "r"(b1));
}
__device__ __forceinline__ unsigned smaddr(const void* p) {
    return (unsigned)__cvta_generic_to_shared(p);
}
__device__ __forceinline__ void cp16(unsigned dst, const void* src) {
    asm volatile("cp.async.cg.shared.global [%0], [%1], 16;" :: "r"(dst), "l"(src));
}

// ---------------------------------------------------------------------------
// Single-pass TF32 GEMM, double-buffered smem, ONE sync per BK=16 chunk.
// (round-8 version, measured qkv=176.6us / proj~45us in the 523us run)
// ---------------------------------------------------------------------------
#define LDP 136

template<int NC, bool PROJ>
__global__ __launch_bounds__(256, 2) void gemm_tf32_kernel(
    const float* __restrict__ Ain, const float* __restrict__ W,
    const float* __restrict__ bias, float* __restrict__ out)
{
    __shared__ float Ash[2][16][LDP];
    __shared__ float Bsh[2][16][LDP];

    const float* A = PROJ ? (const float*)g_att : Ain;

    const int tid  = threadIdx.x;
    const int lane = tid & 31, warp = tid >> 5;
    const int wm = warp >> 1, wn = warp & 1;
    const int gid = lane >> 2, tig = lane & 3;
    const int bm = blockIdx.y * 128, bn = blockIdx.x * 128;

    const int arow  = tid & 127,   acolg = (tid >> 7) * 8;
    const int brow  = tid >> 4,    bcolg = (tid & 15) * 8;

    const float* Aptr = A + (size_t)(bm + arow) * CDIM + acolg;
    const float* Wptr = W + (size_t)brow * NC + bn + bcolg;

    float acc[2][8][4];
    #pragma unroll
    for (int mi = 0; mi < 2; mi++)
        #pragma unroll
        for (int ni = 0; ni < 8; ni++)
            #pragma unroll
            for (int c = 0; c < 4; c++) acc[mi][ni][c] = 0.f;

    float4 va0, va1, vb0, vb1;

#define LOAD_CHUNK(c)  do { \
        const float* ap = Aptr + (c) * 16; \
        const float* wp = Wptr + (size_t)(c) * 16 * NC; \
        va0 = *(const float4*)(ap); \
        va1 = *(const float4*)(ap + 4); \
        vb0 = *(const float4*)(wp); \
        vb1 = *(const float4*)(wp + 4); \
    } while (0)

#define STAGE(BUF)  do { \
        const float* a0 = (const float*)&va0; \
        const float* a1 = (const float*)&va1; \
        _Pragma("unroll") \
        for (int j = 0; j < 4; j++) { \
            Ash[BUF][acolg + j][arow]     = __uint_as_float(f2tf32(a0[j])); \
            Ash[BUF][acolg + 4 + j][arow] = __uint_as_float(f2tf32(a1[j])); \
        } \
        float4 r0 = make_float4(__uint_as_float(f2tf32(vb0.x)), __uint_as_float(f2tf32(vb0.y)), \
                                __uint_as_float(f2tf32(vb0.z)), __uint_as_float(f2tf32(vb0.w))); \
        float4 r1 = make_float4(__uint_as_float(f2tf32(vb1.x)), __uint_as_float(f2tf32(vb1.y)), \
                                __uint_as_float(f2tf32(vb1.z)), __uint_as_float(f2tf32(vb1.w))); \
        *(float4*)&Bsh[BUF][brow][bcolg]     = r0; \
        *(float4*)&Bsh[BUF][brow][bcolg + 4] = r1; \
    } while (0)

    LOAD_CHUNK(0);
    STAGE(0);
    LOAD_CHUNK(1);
    __syncthreads();

    #pragma unroll 1
    for (int c = 0; c < 24; c++) {
        const int cur = c & 1;
        if (c < 23) STAGE(cur ^ 1);
        if (c < 22) LOAD_CHUNK(c + 2);

        #pragma unroll
        for (int ks = 0; ks < 2; ks++) {
            const int k0i = ks * 8 + tig;
            const int k1i = k0i + 4;

            unsigned a[2][4];
            #pragma unroll
            for (int mi = 0; mi < 2; mi++) {
                const int m = wm * 32 + mi * 16 + gid;
                a[mi][0] = __float_as_uint(Ash[cur][k0i][m]);
                a[mi][1] = __float_as_uint(Ash[cur][k0i][m + 8]);
                a[mi][2] = __float_as_uint(Ash[cur][k1i][m]);
                a[mi][3] = __float_as_uint(Ash[cur][k1i][m + 8]);
            }
            #pragma unroll
            for (int ni = 0; ni < 8; ni++) {
                const int n = wn * 64 + ni * 8 + gid;
                unsigned b0 = __float_as_uint(Bsh[cur][k0i][n]);
                unsigned b1 = __float_as_uint(Bsh[cur][k1i][n]);
                mma_tf32(acc[0][ni], a[0], b0, b1);
                mma_tf32(acc[1][ni], a[1], b0, b1);
            }
        }
        __syncthreads();
    }

#undef LOAD_CHUNK
#undef STAGE

    #pragma unroll
    for (int mi = 0; mi < 2; mi++) {
        const int r0 = bm + wm * 32 + mi * 16 + gid;
        const int r1 = r0 + 8;
        #pragma unroll
        for (int ni = 0; ni < 8; ni++) {
            if (PROJ) {
                const int c = bn + wn * 64 + ni * 8 + tig * 2;
                float bx = bias[c], by = bias[c + 1];
                *(float2*)(out + (size_t)r0 * CDIM + c) =
                    make_float2(acc[mi][ni][0] + bx, acc[mi][ni][1] + by);
                *(float2*)(out + (size_t)r1 * CDIM + c) =
                    make_float2(acc[mi][ni][2] + bx, acc[mi][ni][3] + by);
            } else {
                const int which = bn / CDIM;                       // 0=q,1=k,2=v
                const int cloc  = (bn % CDIM) + wn * 64 + ni * 8 + tig * 2;
                const int h = cloc >> 6, dd = cloc & 63;
                float* dst = (which == 0) ? g_q : (which == 1) ? g_k : g_v;
                const float sc = (which == 0) ? SCALE_LOG2E : 1.0f;
                const int b0r = r0 >> 11, t0 = r0 & 2047;
                const int b1r = r1 >> 11, t1 = r1 & 2047;
                float2 v0 = make_float2(__uint_as_float(f2tf32(acc[mi][ni][0] * sc)),
                                        __uint_as_float(f2tf32(acc[mi][ni][1] * sc)));
                float2 v1 = make_float2(__uint_as_float(f2tf32(acc[mi][ni][2] * sc)),
                                        __uint_as_float(f2tf32(acc[mi][ni][3] * sc)));
                *(float2*)(dst + (((size_t)(b0r * NHEAD + h) * TSEQ + t0) << 6) + dd) = v0;
                *(float2*)(dst + (((size_t)(b1r * NHEAD + h) * TSEQ + t1) << 6) + dd) = v1;
            }
        }
    }
}

// ---------------------------------------------------------------------------
// Causal flash attention: round-8 structure (proven 301us) with two local
// tweaks: (1) Q fragments loaded directly from gmem (no Q staging/barrier),
// (2) S-MMA chain split into two 4-deep chains.
// 256 threads, Q tile 128, cp.async double-buffered K/V, 1 sync/tile,
// online softmax as in round 8.  smem 96KB (2 CTAs/SM).
// ---------------------------------------------------------------------------
__device__ __forceinline__ int sw(int row, int col) {
    return row * 64 + (((((unsigned)col >> 2) ^ (row & 7)) << 2) | (col & 3));
}

__global__ __launch_bounds__(256, 2) void flash_attn_kernel()
{
    extern __shared__ float smf[];
    float* Kbuf = smf;             // [2][4096]
    float* Vbuf = smf + 8192;      // [2][4096]
    float* Ps   = smf + 16384;     // [128][64] swizzled (P only)

    const int bh   = blockIdx.y;
    const int qb   = 15 - blockIdx.x;      // heavy q-blocks first
    const int tid  = threadIdx.x;
    const int lane = tid & 31;
    const int warp = tid >> 5;
    const int gid  = lane >> 2;
    const int tig  = lane & 3;

    const float* __restrict__ Qb = g_q + (size_t)bh * TSEQ * HDIM;
    const float* __restrict__ Kb = g_k + (size_t)bh * TSEQ * HDIM;
    const float* __restrict__ Vb = g_v + (size_t)bh * TSEQ * HDIM;

    const int qrow0 = warp * 16 + gid;     // 0..127
    const int qrow1 = qrow0 + 8;
    const int qg0   = qb * 128 + qrow0;
    const int qg1   = qb * 128 + qrow1;

    // ---- preload KV tile 0 into buffer 0 (issue first for max overlap) ----
    {
        const float4* Kg = (const float4*)Kb;
        const float4* Vg = (const float4*)Vb;
        #pragma unroll
        for (int i = 0; i < 4; i++) {
            int idx = i * 256 + tid;
            int row = idx >> 4, c4 = idx & 15;
            int s4 = row * 16 + (c4 ^ (row & 7));
            cp16(smaddr(Kbuf + s4 * 4), Kg + idx);
            cp16(smaddr(Vbuf + s4 * 4), Vg + idx);
        }
        asm volatile("cp.async.commit_group;");
    }

    // ---- Q fragments direct from gmem (pre-rounded tf32, pre-scaled) ----
    unsigned qa[8][4];
    {
        const float* q0 = Qb + (size_t)qg0 * HDIM;
        const float* q1 = Qb + (size_t)qg1 * HDIM;
        #pragma unroll
        for (int kc = 0; kc < 8; kc++) {
            int col = kc * 8 + tig;
            qa[kc][0] = __float_as_uint(q0[col]);
            qa[kc][1] = __float_as_uint(q1[col]);
            qa[kc][2] = __float_as_uint(q0[col + 4]);
            qa[kc][3] = __float_as_uint(q1[col + 4]);
        }
    }

    const int jtmax  = 2 * qb + 1;
    const int mydiag = 2 * qb + (warp >> 2);  // warps 0-3: 2qb, warps 4-7: 2qb+1

    float o[8][4];
    #pragma unroll
    for (int n = 0; n < 8; n++)
        #pragma unroll
        for (int c = 0; c < 4; c++) o[n][c] = 0.f;
    float m0 = -1e30f, m1 = -1e30f, l0 = 0.f, l1 = 0.f;

    #pragma unroll 1
    for (int jt = 0; jt <= jtmax; jt++) {
        const int cur = jt & 1;

        asm volatile("cp.async.wait_group 0;");   // tile jt landed
        __syncthreads();                          // visible; buf[cur^1] free

        // prefetch tile jt+1 into the other buffer (overlaps compute)
        if (jt < jtmax) {
            const float4* Kg = (const float4*)(Kb + (size_t)(jt + 1) * 64 * HDIM);
            const float4* Vg = (const float4*)(Vb + (size_t)(jt + 1) * 64 * HDIM);
            float* Kd = Kbuf + (cur ^ 1) * 4096;
            float* Vd = Vbuf + (cur ^ 1) * 4096;
            #pragma unroll
            for (int i = 0; i < 4; i++) {
                int idx = i * 256 + tid;
                int row = idx >> 4, c4 = idx & 15;
                int s4 = row * 16 + (c4 ^ (row & 7));
                cp16(smaddr(Kd + s4 * 4), Kg + idx);
                cp16(smaddr(Vd + s4 * 4), Vg + idx);
            }
            asm volatile("cp.async.commit_group;");
        }

        if (jt <= mydiag) {
            const float* Ks = Kbuf + cur * 4096;
            const float* Vs = Vbuf + cur * 4096;

            // S = Q K^T: per n, two independent 4-deep MMA chains
            float s[8][4];
            #pragma unroll
            for (int n = 0; n < 8; n++) {
                float sa[4] = {0.f, 0.f, 0.f, 0.f};
                float sb[4] = {0.f, 0.f, 0.f, 0.f};
                const int krow = n * 8 + gid;
                #pragma unroll
                for (int kc = 0; kc < 8; kc += 2) {
                    unsigned b0 = __float_as_uint(Ks[sw(krow, kc * 8 + tig)]);
                    unsigned b1 = __float_as_uint(Ks[sw(krow, kc * 8 + tig + 4)]);
                    mma_tf32(sa, qa[kc], b0, b1);
                    unsigned c0 = __float_as_uint(Ks[sw(krow, kc * 8 + 8 + tig)]);
                    unsigned c1 = __float_as_uint(Ks[sw(krow, kc * 8 + 12 + tig)]);
                    mma_tf32(sb, qa[kc + 1], c0, c1);
                }
                s[n][0] = sa[0] + sb[0];
                s[n][1] = sa[1] + sb[1];
                s[n][2] = sa[2] + sb[2];
                s[n][3] = sa[3] + sb[3];
            }

            // causal mask (diagonal tile only); q pre-scaled so S is log2-scaled
            if (jt == mydiag) {
                const int jbase = jt * 64;
                #pragma unroll
                for (int n = 0; n < 8; n++) {
                    int j0 = jbase + n * 8 + 2 * tig;
                    if (j0 > qg0)     s[n][0] = -1e30f;
                    if (j0 + 1 > qg0) s[n][1] = -1e30f;
                    if (j0 > qg1)     s[n][2] = -1e30f;
                    if (j0 + 1 > qg1) s[n][3] = -1e30f;
                }
            }

            // row max (quad reduce)
            float mx0 = -1e30f, mx1 = -1e30f;
            #pragma unroll
            for (int n = 0; n < 8; n++) {
                mx0 = fmaxf(mx0, fmaxf(s[n][0], s[n][1]));
                mx1 = fmaxf(mx1, fmaxf(s[n][2], s[n][3]));
            }
            mx0 = fmaxf(mx0, __shfl_xor_sync(0xffffffffu, mx0, 1));
            mx0 = fmaxf(mx0, __shfl_xor_sync(0xffffffffu, mx0, 2));
            mx1 = fmaxf(mx1, __shfl_xor_sync(0xffffffffu, mx1, 1));
            mx1 = fmaxf(mx1, __shfl_xor_sync(0xffffffffu, mx1, 2));

            const float mn0 = fmaxf(m0, mx0);
            const float mn1 = fmaxf(m1, mx1);
            const float cr0 = fast_exp2(m0 - mn0);
            const float cr1 = fast_exp2(m1 - mn1);
            m0 = mn0; m1 = mn1;
            l0 *= cr0; l1 *= cr1;
            #pragma unroll
            for (int n = 0; n < 8; n++) {
                o[n][0] *= cr0; o[n][1] *= cr0;
                o[n][2] *= cr1; o[n][3] *= cr1;
            }

            // p = exp2(s - m); accumulate l; store P (own rows only)
            float sum0 = 0.f, sum1 = 0.f;
            #pragma unroll
            for (int n = 0; n < 8; n++) {
                float p00 = fast_exp2(s[n][0] - mn0);
                float p01 = fast_exp2(s[n][1] - mn0);
                float p10 = fast_exp2(s[n][2] - mn1);
                float p11 = fast_exp2(s[n][3] - mn1);
                sum0 += p00 + p01;
                sum1 += p10 + p11;
                int col = n * 8 + 2 * tig;
                *(float2*)&Ps[sw(qrow0, col)] = make_float2(p00, p01);
                *(float2*)&Ps[sw(qrow1, col)] = make_float2(p10, p11);
            }
            sum0 += __shfl_xor_sync(0xffffffffu, sum0, 1);
            sum0 += __shfl_xor_sync(0xffffffffu, sum0, 2);
            sum1 += __shfl_xor_sync(0xffffffffu, sum1, 1);
            sum1 += __shfl_xor_sync(0xffffffffu, sum1, 2);
            l0 += sum0; l1 += sum1;

            __syncwarp();

            // O += P V (16x64 per warp)
            #pragma unroll
            for (int kc = 0; kc < 8; kc++) {
                unsigned pa[4];
                int col = kc * 8 + tig;
                pa[0] = f2tf32(Ps[sw(qrow0, col)]);
                pa[1] = f2tf32(Ps[sw(qrow1, col)]);
                pa[2] = f2tf32(Ps[sw(qrow0, col + 4)]);
                pa[3] = f2tf32(Ps[sw(qrow1, col + 4)]);
                #pragma unroll
                for (int dn = 0; dn < 8; dn++) {
                    unsigned b0 = __float_as_uint(Vs[sw(kc * 8 + tig,     dn * 8 + gid)]);
                    unsigned b1 = __float_as_uint(Vs[sw(kc * 8 + tig + 4, dn * 8 + gid)]);
                    mma_tf32(o[dn], pa, b0, b1);
                }
            }
        }
        // no trailing barrier: next iteration's wait+sync provides the fence
    }

    // ---- normalize and write g_att [B,T,C] ----
    const float inv0 = 1.f / l0;
    const float inv1 = 1.f / l1;
    const int b = bh / NHEAD, h = bh % NHEAD;
    float* base0 = g_att + (size_t)(b * TSEQ + qg0) * CDIM + h * HDIM;
    float* base1 = g_att + (size_t)(b * TSEQ + qg1) * CDIM + h * HDIM;
    #pragma unroll
    for (int dn = 0; dn < 8; dn++) {
        int col = dn * 8 + 2 * tig;
        *(float2*)(base0 + col) = make_float2(o[dn][0] * inv0, o[dn][1] * inv0);
        *(float2*)(base1 + col) = make_float2(o[dn][2] * inv1, o[dn][3] * inv1);
    }
}

// ---------------------------------------------------------------------------
extern "C" void kernel_launch(void* const* d_in, const int* in_sizes, int n_in,
                              void* d_out, int out_size)
{
    const float* x      = (const float*)d_in[0];   // [8,2048,384]
    const float* w_qkv  = (const float*)d_in[1];   // [384,1152]
    const float* w_proj = (const float*)d_in[2];   // [384,384]
    const float* b_proj = (const float*)d_in[3];   // [384]
    float* out = (float*)d_out;                    // [8,2048,384]

    cudaFuncSetAttribute(flash_attn_kernel,
                         cudaFuncAttributeMaxDynamicSharedMemorySize, 98304);

    {
        dim3 grid(C3 / 128, MROWS / 128);          // (9, 128)
        gemm_tf32_kernel<C3, false><<<grid, 256>>>(x, w_qkv, nullptr, nullptr);
    }
    {
        dim3 grid(TSEQ / 128, BATCH * NHEAD);      // (16, 48)
        flash_attn_kernel<<<grid, 256, 98304>>>();
    }
    {
        dim3 grid(CDIM / 128, MROWS / 128);        // (3, 128)
        gemm_tf32_kernel<CDIM, true><<<grid, 256>>>(nullptr, w_proj, b_proj, out);
    }
}

// round 15
// speedup vs baseline: 2.3095x; 1.2005x over previous
#include <cuda_runtime.h>
#include <cuda_bf16.h>
#include <math_constants.h>
#include <cstdint>

// Problem constants
#define BATCH 8
#define TSEQ  2048
#define NHEAD 6
#define HDIM  64
#define CDIM  (NHEAD * HDIM)      // 384
#define C3    (3 * CDIM)          // 1152
#define MROWS (BATCH * TSEQ)      // 16384

#define SCALE_LOG2E 0.18033688011112042f   // (1/8) * log2(e), folded into q

// Scratch (device globals; no runtime allocation allowed)
__device__ float g_q[BATCH * NHEAD * TSEQ * HDIM];   // [B,H,T,D] tf32, pre-scaled
__device__ float g_k[BATCH * NHEAD * TSEQ * HDIM];
__device__ float g_v[BATCH * NHEAD * TSEQ * HDIM];
__device__ float g_att[MROWS * CDIM];                // [B,T,C] tf32-rounded
__device__ float g_xr[MROWS * CDIM];                 // x tf32-rounded

// ---------------------------------------------------------------------------
// Helpers
// ---------------------------------------------------------------------------
__device__ __forceinline__ unsigned f2tf32(float f) {
    unsigned u;
    asm("cvt.rna.tf32.f32 %0, %1;" : "=r"(u) : "f"(f));
    return u;
}
__device__ __forceinline__ float rtf(float f) { return __uint_as_float(f2tf32(f)); }
__device__ __forceinline__ float fast_exp2(float x) {
    float y;
    asm("ex2.approx.f32 %0, %1;" : "=f"(y) : "f"(x));
    return y;
}
__device__ __forceinline__ void mma_tf32(float* d, const unsigned* a, unsigned b0, unsigned b1) {
    asm volatile(
        "mma.sync.aligned.m16n8k8.row.col.f32.tf32.tf32.f32 "
        "{%0,%1,%2,%3},{%4,%5,%6,%7},{%8,%9},{%0,%1,%2,%3};"
        : "+f"(d[0]), "+f"(d[1]), "+f"(d[2]), "+f"(d[3])
        : "r"(a[0]), "r"(a[1]), "r"(a[2]), "r"(a[3]), "r"(b0), "r"(b1));
}
__device__ __forceinline__ unsigned smaddr(const void* p) {
    return (unsigned)__cvta_generic_to_shared(p);
}
__device__ __forceinline__ void cp16(unsigned dst, const void* src) {
    asm volatile("cp.async.cg.shared.global [%0], [%1], 16;" :: "r"(dst), "l"(src));
}

// ---------------------------------------------------------------------------
// Pre-round x to tf32 (elementwise, vectorized)
// ---------------------------------------------------------------------------
__global__ __launch_bounds__(256) void preround_kernel(const float* __restrict__ x)
{
    float4* dst = (float4*)g_xr;
    const float4* src = (const float4*)x;
    int i = blockIdx.x * 256 + threadIdx.x;
    float4 v = src[i];
    dst[i] = make_float4(rtf(v.x), rtf(v.y), rtf(v.z), rtf(v.w));
}

// ---------------------------------------------------------------------------
// Hybrid TF32 GEMM: A staged by cp.async (pre-rounded gmem, 80B-pitch rows,
// conflict-free scalar reads), B staged by register CVT path (round-8 style).
// BM=BN=128, BK=16, 24 chunks, double-buffered, one sync per chunk.
// PROJ=false: A = g_xr, scatter -> g_q (pre-scaled) / g_k / g_v (tf32).
// PROJ=true : A = g_att (tf32-rounded by flash), +bias -> out.
// ---------------------------------------------------------------------------
#define LDP 136
#define APITCH_F 20      // floats per A row (80 bytes)

template<int NC, bool PROJ>
__global__ __launch_bounds__(256, 2) void gemm_tf32_kernel(
    const float* __restrict__ W, const float* __restrict__ bias,
    float* __restrict__ out)
{
    __shared__ float Abuf[2][128 * APITCH_F];   // 2 x 10KB
    __shared__ float Bsh[2][16][LDP];           // 2 x 8.7KB

    const float* A = PROJ ? (const float*)g_att : (const float*)g_xr;

    const int tid  = threadIdx.x;
    const int lane = tid & 31, warp = tid >> 5;
    const int wm = warp >> 1, wn = warp & 1;
    const int gid = lane >> 2, tig = lane & 3;
    const int bm = blockIdx.y * 128, bn = blockIdx.x * 128;

    const int brow  = tid >> 4,  bcolg = (tid & 15) * 8;
    const float* Wptr = W + (size_t)brow * NC + bn + bcolg;

    float acc[2][8][4];
    #pragma unroll
    for (int mi = 0; mi < 2; mi++)
        #pragma unroll
        for (int ni = 0; ni < 8; ni++)
            #pragma unroll
            for (int c = 0; c < 4; c++) acc[mi][ni][c] = 0.f;

    float4 vb0, vb1;

#define LOAD_W(c)  do { \
        const float* wp = Wptr + (size_t)(c) * 16 * NC; \
        vb0 = *(const float4*)(wp); \
        vb1 = *(const float4*)(wp + 4); \
    } while (0)

#define STAGE_B(BUF)  do { \
        float4 r0 = make_float4(rtf(vb0.x), rtf(vb0.y), rtf(vb0.z), rtf(vb0.w)); \
        float4 r1 = make_float4(rtf(vb1.x), rtf(vb1.y), rtf(vb1.z), rtf(vb1.w)); \
        *(float4*)&Bsh[BUF][brow][bcolg]     = r0; \
        *(float4*)&Bsh[BUF][brow][bcolg + 4] = r1; \
    } while (0)

// 512 granules of 16B: idx -> (row = idx>>2, g = idx&3)
#define STAGE_A(c, BUF)  do { \
        _Pragma("unroll") \
        for (int i = 0; i < 2; i++) { \
            const int idx = i * 256 + tid; \
            const int row = idx >> 2, g = idx & 3; \
            cp16(smaddr((char*)&Abuf[BUF][0] + row * 80 + g * 16), \
                 A + (size_t)(bm + row) * CDIM + (c) * 16 + g * 4); \
        } \
        asm volatile("cp.async.commit_group;"); \
    } while (0)

    // prologue: A(0) in flight, B(0) staged, W(1) loaded
    STAGE_A(0, 0);
    LOAD_W(0);
    STAGE_B(0);
    LOAD_W(1);
    asm volatile("cp.async.wait_group 0;");
    __syncthreads();

    #pragma unroll 1
    for (int c = 0; c < 24; c++) {
        const int cur = c & 1;
        if (c < 23) {
            STAGE_B(cur ^ 1);          // B chunk c+1 from regs
            STAGE_A(c + 1, cur ^ 1);   // A chunk c+1 via cp.async
        }
        if (c < 22) LOAD_W(c + 2);

        const float* Ab = &Abuf[cur][0];
        #pragma unroll
        for (int ks = 0; ks < 2; ks++) {
            const int k0i = ks * 8 + tig;
            const int k1i = k0i + 4;

            unsigned a[2][4];
            #pragma unroll
            for (int mi = 0; mi < 2; mi++) {
                const int m = wm * 32 + mi * 16 + gid;
                a[mi][0] = __float_as_uint(Ab[m * APITCH_F + k0i]);
                a[mi][1] = __float_as_uint(Ab[(m + 8) * APITCH_F + k0i]);
                a[mi][2] = __float_as_uint(Ab[m * APITCH_F + k1i]);
                a[mi][3] = __float_as_uint(Ab[(m + 8) * APITCH_F + k1i]);
            }
            #pragma unroll
            for (int ni = 0; ni < 8; ni++) {
                const int n = wn * 64 + ni * 8 + gid;
                unsigned b0 = __float_as_uint(Bsh[cur][k0i][n]);
                unsigned b1 = __float_as_uint(Bsh[cur][k1i][n]);
                mma_tf32(acc[0][ni], a[0], b0, b1);
                mma_tf32(acc[1][ni], a[1], b0, b1);
            }
        }
        asm volatile("cp.async.wait_group 0;");
        __syncthreads();
    }

#undef LOAD_W
#undef STAGE_B
#undef STAGE_A

    // ---- epilogue ----
    #pragma unroll
    for (int mi = 0; mi < 2; mi++) {
        const int r0 = bm + wm * 32 + mi * 16 + gid;
        const int r1 = r0 + 8;
        #pragma unroll
        for (int ni = 0; ni < 8; ni++) {
            if (PROJ) {
                const int c = bn + wn * 64 + ni * 8 + tig * 2;
                float bx = bias[c], by = bias[c + 1];
                *(float2*)(out + (size_t)r0 * CDIM + c) =
                    make_float2(acc[mi][ni][0] + bx, acc[mi][ni][1] + by);
                *(float2*)(out + (size_t)r1 * CDIM + c) =
                    make_float2(acc[mi][ni][2] + bx, acc[mi][ni][3] + by);
            } else {
                const int which = bn / CDIM;                       // 0=q,1=k,2=v
                const int cloc  = (bn % CDIM) + wn * 64 + ni * 8 + tig * 2;
                const int h = cloc >> 6, dd = cloc & 63;
                float* dst = (which == 0) ? g_q : (which == 1) ? g_k : g_v;
                const float sc = (which == 0) ? SCALE_LOG2E : 1.0f;
                const int b0r = r0 >> 11, t0 = r0 & 2047;
                const int b1r = r1 >> 11, t1 = r1 & 2047;
                float2 v0 = make_float2(rtf(acc[mi][ni][0] * sc), rtf(acc[mi][ni][1] * sc));
                float2 v1 = make_float2(rtf(acc[mi][ni][2] * sc), rtf(acc[mi][ni][3] * sc));
                *(float2*)(dst + (((size_t)(b0r * NHEAD + h) * TSEQ + t0) << 6) + dd) = v0;
                *(float2*)(dst + (((size_t)(b1r * NHEAD + h) * TSEQ + t1) << 6) + dd) = v1;
            }
        }
    }
}

// ---------------------------------------------------------------------------
// Causal flash attention: EXACT round-8 structure (proven ~302us), with the
// single change that the final g_att store is tf32-rounded (feeds proj's
// cp.async staging).  256 threads, Q tile 128, cp.async double-buffered K/V,
// one sync per KV tile, online softmax, smem 96KB (2 CTAs/SM).
// ---------------------------------------------------------------------------
__device__ __forceinline__ int sw(int row, int col) {
    return row * 64 + (((((unsigned)col >> 2) ^ (row & 7)) << 2) | (col & 3));
}

__global__ __launch_bounds__(256, 2) void flash_attn_kernel()
{
    extern __shared__ float smf[];
    float* Kbuf = smf;             // [2][4096]
    float* Vbuf = smf + 8192;      // [2][4096]
    float* Ps   = smf + 16384;     // [128][64] swizzled (Q staging, then P)

    const int bh   = blockIdx.y;
    const int qb   = 15 - blockIdx.x;      // heavy q-blocks first
    const int tid  = threadIdx.x;
    const int lane = tid & 31;
    const int warp = tid >> 5;
    const int gid  = lane >> 2;
    const int tig  = lane & 3;

    const float* __restrict__ Qb = g_q + (size_t)bh * TSEQ * HDIM;
    const float* __restrict__ Kb = g_k + (size_t)bh * TSEQ * HDIM;
    const float* __restrict__ Vb = g_v + (size_t)bh * TSEQ * HDIM;

    const int qrow0 = warp * 16 + gid;     // 0..127
    const int qrow1 = qrow0 + 8;
    const int qg0   = qb * 128 + qrow0;
    const int qg1   = qb * 128 + qrow1;

    // ---- stage Q tile (128x64) into Ps, swizzled ----
    {
        const float4* Qg = (const float4*)(Qb + (size_t)qb * 128 * HDIM);
        float4* P4 = (float4*)Ps;
        #pragma unroll
        for (int i = 0; i < 8; i++) {
            int idx = i * 256 + tid;       // 0..2047
            int row = idx >> 4, c4 = idx & 15;
            P4[row * 16 + (c4 ^ (row & 7))] = Qg[idx];
        }
    }

    // ---- preload KV tile 0 into buffer 0 ----
    {
        const float4* Kg = (const float4*)Kb;
        const float4* Vg = (const float4*)Vb;
        #pragma unroll
        for (int i = 0; i < 4; i++) {
            int idx = i * 256 + tid;       // 0..1023
            int row = idx >> 4, c4 = idx & 15;
            int s4 = row * 16 + (c4 ^ (row & 7));
            cp16(smaddr(Kbuf + s4 * 4), Kg + idx);
            cp16(smaddr(Vbuf + s4 * 4), Vg + idx);
        }
        asm volatile("cp.async.commit_group;");
    }
    __syncthreads();   // Q staging visible

    unsigned qa[8][4];
    #pragma unroll
    for (int kc = 0; kc < 8; kc++) {
        int col = kc * 8 + tig;
        qa[kc][0] = __float_as_uint(Ps[sw(qrow0, col)]);
        qa[kc][1] = __float_as_uint(Ps[sw(qrow1, col)]);
        qa[kc][2] = __float_as_uint(Ps[sw(qrow0, col + 4)]);
        qa[kc][3] = __float_as_uint(Ps[sw(qrow1, col + 4)]);
    }
    // each warp reads only its own 16 rows, which only it overwrites with P later

    const int jtmax  = 2 * qb + 1;
    const int mydiag = 2 * qb + (warp >> 2);  // warps 0-3: 2qb, warps 4-7: 2qb+1

    float o[8][4];
    #pragma unroll
    for (int n = 0; n < 8; n++)
        #pragma unroll
        for (int c = 0; c < 4; c++) o[n][c] = 0.f;
    float m0 = -1e30f, m1 = -1e30f, l0 = 0.f, l1 = 0.f;

    #pragma unroll 1
    for (int jt = 0; jt <= jtmax; jt++) {
        const int cur = jt & 1;

        asm volatile("cp.async.wait_group 0;");   // tile jt landed
        __syncthreads();                          // visible; buf[cur^1] free

        // issue prefetch of tile jt+1 into the other buffer (overlaps compute)
        if (jt < jtmax) {
            const float4* Kg = (const float4*)(Kb + (size_t)(jt + 1) * 64 * HDIM);
            const float4* Vg = (const float4*)(Vb + (size_t)(jt + 1) * 64 * HDIM);
            float* Kd = Kbuf + (cur ^ 1) * 4096;
            float* Vd = Vbuf + (cur ^ 1) * 4096;
            #pragma unroll
            for (int i = 0; i < 4; i++) {
                int idx = i * 256 + tid;
                int row = idx >> 4, c4 = idx & 15;
                int s4 = row * 16 + (c4 ^ (row & 7));
                cp16(smaddr(Kd + s4 * 4), Kg + idx);
                cp16(smaddr(Vd + s4 * 4), Vg + idx);
            }
            asm volatile("cp.async.commit_group;");
        }

        if (jt <= mydiag) {
            const float* Ks = Kbuf + cur * 4096;
            const float* Vs = Vbuf + cur * 4096;

            // S = Q K^T (16x64 per warp); q pre-scaled, so S is log2-scaled
            float s[8][4];
            #pragma unroll
            for (int n = 0; n < 8; n++) {
                s[n][0] = s[n][1] = s[n][2] = s[n][3] = 0.f;
                #pragma unroll
                for (int kc = 0; kc < 8; kc++) {
                    unsigned b0 = __float_as_uint(Ks[sw(n * 8 + gid, kc * 8 + tig)]);
                    unsigned b1 = __float_as_uint(Ks[sw(n * 8 + gid, kc * 8 + tig + 4)]);
                    mma_tf32(s[n], qa[kc], b0, b1);
                }
            }

            // causal mask (diagonal tile only)
            if (jt == mydiag) {
                const int jbase = jt * 64;
                #pragma unroll
                for (int n = 0; n < 8; n++) {
                    int j0 = jbase + n * 8 + 2 * tig;
                    if (j0 > qg0)     s[n][0] = -1e30f;
                    if (j0 + 1 > qg0) s[n][1] = -1e30f;
                    if (j0 > qg1)     s[n][2] = -1e30f;
                    if (j0 + 1 > qg1) s[n][3] = -1e30f;
                }
            }

            // row max (quad reduce)
            float mx0 = -1e30f, mx1 = -1e30f;
            #pragma unroll
            for (int n = 0; n < 8; n++) {
                mx0 = fmaxf(mx0, fmaxf(s[n][0], s[n][1]));
                mx1 = fmaxf(mx1, fmaxf(s[n][2], s[n][3]));
            }
            mx0 = fmaxf(mx0, __shfl_xor_sync(0xffffffffu, mx0, 1));
            mx0 = fmaxf(mx0, __shfl_xor_sync(0xffffffffu, mx0, 2));
            mx1 = fmaxf(mx1, __shfl_xor_sync(0xffffffffu, mx1, 1));
            mx1 = fmaxf(mx1, __shfl_xor_sync(0xffffffffu, mx1, 2));

            const float mn0 = fmaxf(m0, mx0);
            const float mn1 = fmaxf(m1, mx1);
            const float cr0 = fast_exp2(m0 - mn0);
            const float cr1 = fast_exp2(m1 - mn1);
            m0 = mn0; m1 = mn1;
            l0 *= cr0; l1 *= cr1;
            #pragma unroll
            for (int n = 0; n < 8; n++) {
                o[n][0] *= cr0; o[n][1] *= cr0;
                o[n][2] *= cr1; o[n][3] *= cr1;
            }

            // p = exp2(s - m); accumulate l; store P (own rows only)
            float sum0 = 0.f, sum1 = 0.f;
            #pragma unroll
            for (int n = 0; n < 8; n++) {
                float p00 = fast_exp2(s[n][0] - mn0);
                float p01 = fast_exp2(s[n][1] - mn0);
                float p10 = fast_exp2(s[n][2] - mn1);
                float p11 = fast_exp2(s[n][3] - mn1);
                sum0 += p00 + p01;
                sum1 += p10 + p11;
                int col = n * 8 + 2 * tig;
                *(float2*)&Ps[sw(qrow0, col)] = make_float2(p00, p01);
                *(float2*)&Ps[sw(qrow1, col)] = make_float2(p10, p11);
            }
            sum0 += __shfl_xor_sync(0xffffffffu, sum0, 1);
            sum0 += __shfl_xor_sync(0xffffffffu, sum0, 2);
            sum1 += __shfl_xor_sync(0xffffffffu, sum1, 1);
            sum1 += __shfl_xor_sync(0xffffffffu, sum1, 2);
            l0 += sum0; l1 += sum1;

            __syncwarp();

            // O += P V (16x64 per warp)
            #pragma unroll
            for (int kc = 0; kc < 8; kc++) {
                unsigned pa[4];
                int col = kc * 8 + tig;
                pa[0] = f2tf32(Ps[sw(qrow0, col)]);
                pa[1] = f2tf32(Ps[sw(qrow1, col)]);
                pa[2] = f2tf32(Ps[sw(qrow0, col + 4)]);
                pa[3] = f2tf32(Ps[sw(qrow1, col + 4)]);
                #pragma unroll
                for (int dn = 0; dn < 8; dn++) {
                    unsigned b0 = __float_as_uint(Vs[sw(kc * 8 + tig,     dn * 8 + gid)]);
                    unsigned b1 = __float_as_uint(Vs[sw(kc * 8 + tig + 4, dn * 8 + gid)]);
                    mma_tf32(o[dn], pa, b0, b1);
                }
            }
        }
        // no trailing barrier: next iteration's wait+sync provides the fence
    }

    // ---- normalize, tf32-round, write g_att [B,T,C] ----
    const float inv0 = 1.f / l0;
    const float inv1 = 1.f / l1;
    const int b = bh / NHEAD, h = bh % NHEAD;
    float* base0 = g_att + (size_t)(b * TSEQ + qg0) * CDIM + h * HDIM;
    float* base1 = g_att + (size_t)(b * TSEQ + qg1) * CDIM + h * HDIM;
    #pragma unroll
    for (int dn = 0; dn < 8; dn++) {
        int col = dn * 8 + 2 * tig;
        *(float2*)(base0 + col) = make_float2(rtf(o[dn][0] * inv0), rtf(o[dn][1] * inv0));
        *(float2*)(base1 + col) = make_float2(rtf(o[dn][2] * inv1), rtf(o[dn][3] * inv1));
    }
}

// ---------------------------------------------------------------------------
extern "C" void kernel_launch(void* const* d_in, const int* in_sizes, int n_in,
                              void* d_out, int out_size)
{
    const float* x      = (const float*)d_in[0];   // [8,2048,384]
    const float* w_qkv  = (const float*)d_in[1];   // [384,1152]
    const float* w_proj = (const float*)d_in[2];   // [384,384]
    const float* b_proj = (const float*)d_in[3];   // [384]
    float* out = (float*)d_out;                    // [8,2048,384]

    cudaFuncSetAttribute(flash_attn_kernel,
                         cudaFuncAttributeMaxDynamicSharedMemorySize, 98304);

    preround_kernel<<<MROWS * CDIM / 4 / 256, 256>>>(x);
    {
        dim3 grid(C3 / 128, MROWS / 128);          // (9, 128)
        gemm_tf32_kernel<C3, false><<<grid, 256>>>(w_qkv, nullptr, nullptr);
    }
    {
        dim3 grid(TSEQ / 128, BATCH * NHEAD);      // (16, 48)
        flash_attn_kernel<<<grid, 256, 98304>>>();
    }
    {
        dim3 grid(CDIM / 128, MROWS / 128);        // (3, 128)
        gemm_tf32_kernel<CDIM, true><<<grid, 256>>>(w_proj, b_proj, out);
    }
}

// round 16
// speedup vs baseline: 2.3227x; 1.0057x over previous
#include <cuda_runtime.h>
#include <cuda_bf16.h>
#include <math_constants.h>
#include <cstdint>

// Problem constants
#define BATCH 8
#define TSEQ  2048
#define NHEAD 6
#define HDIM  64
#define CDIM  (NHEAD * HDIM)      // 384
#define C3    (3 * CDIM)          // 1152
#define MROWS (BATCH * TSEQ)      // 16384

#define SCALE_LOG2E 0.18033688011112042f   // (1/8) * log2(e), folded into q

// Scratch (device globals; no runtime allocation allowed)
__device__ float g_q[BATCH * NHEAD * TSEQ * HDIM];   // [B,H,T,D] tf32, pre-scaled
__device__ float g_k[BATCH * NHEAD * TSEQ * HDIM];
__device__ float g_v[BATCH * NHEAD * TSEQ * HDIM];
__device__ float g_att[MROWS * CDIM];                // [B,T,C] tf32-rounded

// ---------------------------------------------------------------------------
// Helpers
// ---------------------------------------------------------------------------
__device__ __forceinline__ unsigned f2tf32(float f) {
    unsigned u;
    asm("cvt.rna.tf32.f32 %0, %1;" : "=r"(u) : "f"(f));
    return u;
}
__device__ __forceinline__ float rtf(float f) { return __uint_as_float(f2tf32(f)); }
__device__ __forceinline__ float fast_exp2(float x) {
    float y;
    asm("ex2.approx.f32 %0, %1;" : "=f"(y) : "f"(x));
    return y;
}
__device__ __forceinline__ void mma_tf32(float* d, const unsigned* a, unsigned b0, unsigned b1) {
    asm volatile(
        "mma.sync.aligned.m16n8k8.row.col.f32.tf32.tf32.f32 "
        "{%0,%1,%2,%3},{%4,%5,%6,%7},{%8,%9},{%0,%1,%2,%3};"
        : "+f"(d[0]), "+f"(d[1]), "+f"(d[2]), "+f"(d[3])
        : "r"(a[0]), "r"(a[1]), "r"(a[2]), "r"(a[3]), "r"(b0), "r"(b1));
}
__device__ __forceinline__ unsigned smaddr(const void* p) {
    return (unsigned)__cvta_generic_to_shared(p);
}
__device__ __forceinline__ void cp16(unsigned dst, const void* src) {
    asm volatile("cp.async.cg.shared.global [%0], [%1], 16;" :: "r"(dst), "l"(src));
}

// ---------------------------------------------------------------------------
// Hybrid TF32 GEMM (generalized over TPB / BM):
//   A staged by cp.async into 80B-pitch rows (conflict-free scalar reads),
//   B staged by register-CVT path.  BK=16, 24 chunks, double-buffered,
//   one sync per chunk.
// PROJ=false: TPB=256, BM=128.  A = x (raw fp32; tf32-CVT at fragment read),
//             scatter -> g_q (pre-scaled) / g_k / g_v (tf32-rounded).
// PROJ=true : TPB=128, BM=64.   A = g_att (already tf32), +bias -> out.
// ---------------------------------------------------------------------------
#define LDP 136
#define APITCH_F 20      // floats per A row (80 bytes)

template<int NC, bool PROJ, int TPB, int BM>
__global__ __launch_bounds__(TPB, 2) void gemm_tf32_kernel(
    const float* __restrict__ Ain, const float* __restrict__ W,
    const float* __restrict__ bias, float* __restrict__ out)
{
    __shared__ float Abuf[2][BM * APITCH_F];
    __shared__ float Bsh[2][16][LDP];

    const float* A = PROJ ? (const float*)g_att : Ain;

    const int tid  = threadIdx.x;
    const int lane = tid & 31, warp = tid >> 5;
    const int wm = warp >> 1, wn = warp & 1;          // (TPB/64) m-tiles x 2 n-tiles
    const int gid = lane >> 2, tig = lane & 3;
    const int bm = blockIdx.y * BM, bn = blockIdx.x * 128;

    constexpr int IB = 256 / TPB;    // B-staging iterations (256 float4 slots)
    constexpr int IA = BM * 4 / TPB; // A-staging iterations (BM*4 16B granules)

    float acc[2][8][4];
    #pragma unroll
    for (int mi = 0; mi < 2; mi++)
        #pragma unroll
        for (int ni = 0; ni < 8; ni++)
            #pragma unroll
            for (int c = 0; c < 4; c++) acc[mi][ni][c] = 0.f;

    float4 vbr[IB][2];

#define LOAD_W(c)  do { \
        _Pragma("unroll") \
        for (int i = 0; i < IB; i++) { \
            const int idx = i * TPB + tid; \
            const int br = idx >> 4, bc = (idx & 15) * 8; \
            const float* wp = W + (size_t)((c) * 16 + br) * NC + bn + bc; \
            vbr[i][0] = *(const float4*)(wp); \
            vbr[i][1] = *(const float4*)(wp + 4); \
        } \
    } while (0)

#define STAGE_B(BUF)  do { \
        _Pragma("unroll") \
        for (int i = 0; i < IB; i++) { \
            const int idx = i * TPB + tid; \
            const int br = idx >> 4, bc = (idx & 15) * 8; \
            float4 q0 = vbr[i][0], q1 = vbr[i][1]; \
            *(float4*)&Bsh[BUF][br][bc]     = make_float4(rtf(q0.x), rtf(q0.y), rtf(q0.z), rtf(q0.w)); \
            *(float4*)&Bsh[BUF][br][bc + 4] = make_float4(rtf(q1.x), rtf(q1.y), rtf(q1.z), rtf(q1.w)); \
        } \
    } while (0)

#define STAGE_A(c, BUF)  do { \
        _Pragma("unroll") \
        for (int i = 0; i < IA; i++) { \
            const int idx = i * TPB + tid; \
            const int row = idx >> 2, g = idx & 3; \
            cp16(smaddr((char*)&Abuf[BUF][0] + row * 80 + g * 16), \
                 A + (size_t)(bm + row) * CDIM + (c) * 16 + g * 4); \
        } \
        asm volatile("cp.async.commit_group;"); \
    } while (0)

    // prologue
    STAGE_A(0, 0);
    LOAD_W(0);
    STAGE_B(0);
    LOAD_W(1);
    asm volatile("cp.async.wait_group 0;");
    __syncthreads();

    #pragma unroll 1
    for (int c = 0; c < 24; c++) {
        const int cur = c & 1;
        if (c < 23) {
            STAGE_B(cur ^ 1);
            STAGE_A(c + 1, cur ^ 1);
        }
        if (c < 22) LOAD_W(c + 2);

        const float* Ab = &Abuf[cur][0];
        #pragma unroll
        for (int ks = 0; ks < 2; ks++) {
            const int k0i = ks * 8 + tig;
            const int k1i = k0i + 4;

            unsigned a[2][4];
            #pragma unroll
            for (int mi = 0; mi < 2; mi++) {
                const int m = wm * 32 + mi * 16 + gid;
                if (PROJ) {   // A already tf32
                    a[mi][0] = __float_as_uint(Ab[m * APITCH_F + k0i]);
                    a[mi][1] = __float_as_uint(Ab[(m + 8) * APITCH_F + k0i]);
                    a[mi][2] = __float_as_uint(Ab[m * APITCH_F + k1i]);
                    a[mi][3] = __float_as_uint(Ab[(m + 8) * APITCH_F + k1i]);
                } else {      // raw fp32: round at read
                    a[mi][0] = f2tf32(Ab[m * APITCH_F + k0i]);
                    a[mi][1] = f2tf32(Ab[(m + 8) * APITCH_F + k0i]);
                    a[mi][2] = f2tf32(Ab[m * APITCH_F + k1i]);
                    a[mi][3] = f2tf32(Ab[(m + 8) * APITCH_F + k1i]);
                }
            }
            #pragma unroll
            for (int ni = 0; ni < 8; ni++) {
                const int n = wn * 64 + ni * 8 + gid;
                unsigned b0 = __float_as_uint(Bsh[cur][k0i][n]);
                unsigned b1 = __float_as_uint(Bsh[cur][k1i][n]);
                mma_tf32(acc[0][ni], a[0], b0, b1);
                mma_tf32(acc[1][ni], a[1], b0, b1);
            }
        }
        asm volatile("cp.async.wait_group 0;");
        __syncthreads();
    }

#undef LOAD_W
#undef STAGE_B
#undef STAGE_A

    // ---- epilogue ----
    #pragma unroll
    for (int mi = 0; mi < 2; mi++) {
        const int r0 = bm + wm * 32 + mi * 16 + gid;
        const int r1 = r0 + 8;
        #pragma unroll
        for (int ni = 0; ni < 8; ni++) {
            if (PROJ) {
                const int c = bn + wn * 64 + ni * 8 + tig * 2;
                float bx = bias[c], by = bias[c + 1];
                *(float2*)(out + (size_t)r0 * CDIM + c) =
                    make_float2(acc[mi][ni][0] + bx, acc[mi][ni][1] + by);
                *(float2*)(out + (size_t)r1 * CDIM + c) =
                    make_float2(acc[mi][ni][2] + bx, acc[mi][ni][3] + by);
            } else {
                const int which = bn / CDIM;                       // 0=q,1=k,2=v
                const int cloc  = (bn % CDIM) + wn * 64 + ni * 8 + tig * 2;
                const int h = cloc >> 6, dd = cloc & 63;
                float* dst = (which == 0) ? g_q : (which == 1) ? g_k : g_v;
                const float sc = (which == 0) ? SCALE_LOG2E : 1.0f;
                const int b0r = r0 >> 11, t0 = r0 & 2047;
                const int b1r = r1 >> 11, t1 = r1 & 2047;
                float2 v0 = make_float2(rtf(acc[mi][ni][0] * sc), rtf(acc[mi][ni][1] * sc));
                float2 v1 = make_float2(rtf(acc[mi][ni][2] * sc), rtf(acc[mi][ni][3] * sc));
                *(float2*)(dst + (((size_t)(b0r * NHEAD + h) * TSEQ + t0) << 6) + dd) = v0;
                *(float2*)(dst + (((size_t)(b1r * NHEAD + h) * TSEQ + t1) << 6) + dd) = v1;
            }
        }
    }
}

// ---------------------------------------------------------------------------
// Causal flash attention: round-8 structure (proven), tf32-rounded g_att
// stores.  256 threads, Q tile 128, cp.async double-buffered K/V, one sync
// per KV tile, online softmax, smem 96KB (2 CTAs/SM).  FROZEN.
// ---------------------------------------------------------------------------
__device__ __forceinline__ int sw(int row, int col) {
    return row * 64 + (((((unsigned)col >> 2) ^ (row & 7)) << 2) | (col & 3));
}

__global__ __launch_bounds__(256, 2) void flash_attn_kernel()
{
    extern __shared__ float smf[];
    float* Kbuf = smf;             // [2][4096]
    float* Vbuf = smf + 8192;      // [2][4096]
    float* Ps   = smf + 16384;     // [128][64] swizzled (Q staging, then P)

    const int bh   = blockIdx.y;
    const int qb   = 15 - blockIdx.x;      // heavy q-blocks first
    const int tid  = threadIdx.x;
    const int lane = tid & 31;
    const int warp = tid >> 5;
    const int gid  = lane >> 2;
    const int tig  = lane & 3;

    const float* __restrict__ Qb = g_q + (size_t)bh * TSEQ * HDIM;
    const float* __restrict__ Kb = g_k + (size_t)bh * TSEQ * HDIM;
    const float* __restrict__ Vb = g_v + (size_t)bh * TSEQ * HDIM;

    const int qrow0 = warp * 16 + gid;     // 0..127
    const int qrow1 = qrow0 + 8;
    const int qg0   = qb * 128 + qrow0;
    const int qg1   = qb * 128 + qrow1;

    // ---- stage Q tile (128x64) into Ps, swizzled ----
    {
        const float4* Qg = (const float4*)(Qb + (size_t)qb * 128 * HDIM);
        float4* P4 = (float4*)Ps;
        #pragma unroll
        for (int i = 0; i < 8; i++) {
            int idx = i * 256 + tid;       // 0..2047
            int row = idx >> 4, c4 = idx & 15;
            P4[row * 16 + (c4 ^ (row & 7))] = Qg[idx];
        }
    }

    // ---- preload KV tile 0 into buffer 0 ----
    {
        const float4* Kg = (const float4*)Kb;
        const float4* Vg = (const float4*)Vb;
        #pragma unroll
        for (int i = 0; i < 4; i++) {
            int idx = i * 256 + tid;       // 0..1023
            int row = idx >> 4, c4 = idx & 15;
            int s4 = row * 16 + (c4 ^ (row & 7));
            cp16(smaddr(Kbuf + s4 * 4), Kg + idx);
            cp16(smaddr(Vbuf + s4 * 4), Vg + idx);
        }
        asm volatile("cp.async.commit_group;");
    }
    __syncthreads();   // Q staging visible

    unsigned qa[8][4];
    #pragma unroll
    for (int kc = 0; kc < 8; kc++) {
        int col = kc * 8 + tig;
        qa[kc][0] = __float_as_uint(Ps[sw(qrow0, col)]);
        qa[kc][1] = __float_as_uint(Ps[sw(qrow1, col)]);
        qa[kc][2] = __float_as_uint(Ps[sw(qrow0, col + 4)]);
        qa[kc][3] = __float_as_uint(Ps[sw(qrow1, col + 4)]);
    }

    const int jtmax  = 2 * qb + 1;
    const int mydiag = 2 * qb + (warp >> 2);

    float o[8][4];
    #pragma unroll
    for (int n = 0; n < 8; n++)
        #pragma unroll
        for (int c = 0; c < 4; c++) o[n][c] = 0.f;
    float m0 = -1e30f, m1 = -1e30f, l0 = 0.f, l1 = 0.f;

    #pragma unroll 1
    for (int jt = 0; jt <= jtmax; jt++) {
        const int cur = jt & 1;

        asm volatile("cp.async.wait_group 0;");
        __syncthreads();

        if (jt < jtmax) {
            const float4* Kg = (const float4*)(Kb + (size_t)(jt + 1) * 64 * HDIM);
            const float4* Vg = (const float4*)(Vb + (size_t)(jt + 1) * 64 * HDIM);
            float* Kd = Kbuf + (cur ^ 1) * 4096;
            float* Vd = Vbuf + (cur ^ 1) * 4096;
            #pragma unroll
            for (int i = 0; i < 4; i++) {
                int idx = i * 256 + tid;
                int row = idx >> 4, c4 = idx & 15;
                int s4 = row * 16 + (c4 ^ (row & 7));
                cp16(smaddr(Kd + s4 * 4), Kg + idx);
                cp16(smaddr(Vd + s4 * 4), Vg + idx);
            }
            asm volatile("cp.async.commit_group;");
        }

        if (jt <= mydiag) {
            const float* Ks = Kbuf + cur * 4096;
            const float* Vs = Vbuf + cur * 4096;

            float s[8][4];
            #pragma unroll
            for (int n = 0; n < 8; n++) {
                s[n][0] = s[n][1] = s[n][2] = s[n][3] = 0.f;
                #pragma unroll
                for (int kc = 0; kc < 8; kc++) {
                    unsigned b0 = __float_as_uint(Ks[sw(n * 8 + gid, kc * 8 + tig)]);
                    unsigned b1 = __float_as_uint(Ks[sw(n * 8 + gid, kc * 8 + tig + 4)]);
                    mma_tf32(s[n], qa[kc], b0, b1);
                }
            }

            if (jt == mydiag) {
                const int jbase = jt * 64;
                #pragma unroll
                for (int n = 0; n < 8; n++) {
                    int j0 = jbase + n * 8 + 2 * tig;
                    if (j0 > qg0)     s[n][0] = -1e30f;
                    if (j0 + 1 > qg0) s[n][1] = -1e30f;
                    if (j0 > qg1)     s[n][2] = -1e30f;
                    if (j0 + 1 > qg1) s[n][3] = -1e30f;
                }
            }

            float mx0 = -1e30f, mx1 = -1e30f;
            #pragma unroll
            for (int n = 0; n < 8; n++) {
                mx0 = fmaxf(mx0, fmaxf(s[n][0], s[n][1]));
                mx1 = fmaxf(mx1, fmaxf(s[n][2], s[n][3]));
            }
            mx0 = fmaxf(mx0, __shfl_xor_sync(0xffffffffu, mx0, 1));
            mx0 = fmaxf(mx0, __shfl_xor_sync(0xffffffffu, mx0, 2));
            mx1 = fmaxf(mx1, __shfl_xor_sync(0xffffffffu, mx1, 1));
            mx1 = fmaxf(mx1, __shfl_xor_sync(0xffffffffu, mx1, 2));

            const float mn0 = fmaxf(m0, mx0);
            const float mn1 = fmaxf(m1, mx1);
            const float cr0 = fast_exp2(m0 - mn0);
            const float cr1 = fast_exp2(m1 - mn1);
            m0 = mn0; m1 = mn1;
            l0 *= cr0; l1 *= cr1;
            #pragma unroll
            for (int n = 0; n < 8; n++) {
                o[n][0] *= cr0; o[n][1] *= cr0;
                o[n][2] *= cr1; o[n][3] *= cr1;
            }

            float sum0 = 0.f, sum1 = 0.f;
            #pragma unroll
            for (int n = 0; n < 8; n++) {
                float p00 = fast_exp2(s[n][0] - mn0);
                float p01 = fast_exp2(s[n][1] - mn0);
                float p10 = fast_exp2(s[n][2] - mn1);
                float p11 = fast_exp2(s[n][3] - mn1);
                sum0 += p00 + p01;
                sum1 += p10 + p11;
                int col = n * 8 + 2 * tig;
                *(float2*)&Ps[sw(qrow0, col)] = make_float2(p00, p01);
                *(float2*)&Ps[sw(qrow1, col)] = make_float2(p10, p11);
            }
            sum0 += __shfl_xor_sync(0xffffffffu, sum0, 1);
            sum0 += __shfl_xor_sync(0xffffffffu, sum0, 2);
            sum1 += __shfl_xor_sync(0xffffffffu, sum1, 1);
            sum1 += __shfl_xor_sync(0xffffffffu, sum1, 2);
            l0 += sum0; l1 += sum1;

            __syncwarp();

            #pragma unroll
            for (int kc = 0; kc < 8; kc++) {
                unsigned pa[4];
                int col = kc * 8 + tig;
                pa[0] = f2tf32(Ps[sw(qrow0, col)]);
                pa[1] = f2tf32(Ps[sw(qrow1, col)]);
                pa[2] = f2tf32(Ps[sw(qrow0, col + 4)]);
                pa[3] = f2tf32(Ps[sw(qrow1, col + 4)]);
                #pragma unroll
                for (int dn = 0; dn < 8; dn++) {
                    unsigned b0 = __float_as_uint(Vs[sw(kc * 8 + tig,     dn * 8 + gid)]);
                    unsigned b1 = __float_as_uint(Vs[sw(kc * 8 + tig + 4, dn * 8 + gid)]);
                    mma_tf32(o[dn], pa, b0, b1);
                }
            }
        }
    }

    // ---- normalize, tf32-round, write g_att [B,T,C] ----
    const float inv0 = 1.f / l0;
    const float inv1 = 1.f / l1;
    const int b = bh / NHEAD, h = bh % NHEAD;
    float* base0 = g_att + (size_t)(b * TSEQ + qg0) * CDIM + h * HDIM;
    float* base1 = g_att + (size_t)(b * TSEQ + qg1) * CDIM + h * HDIM;
    #pragma unroll
    for (int dn = 0; dn < 8; dn++) {
        int col = dn * 8 + 2 * tig;
        *(float2*)(base0 + col) = make_float2(rtf(o[dn][0] * inv0), rtf(o[dn][1] * inv0));
        *(float2*)(base1 + col) = make_float2(rtf(o[dn][2] * inv1), rtf(o[dn][3] * inv1));
    }
}

// ---------------------------------------------------------------------------
extern "C" void kernel_launch(void* const* d_in, const int* in_sizes, int n_in,
                              void* d_out, int out_size)
{
    const float* x      = (const float*)d_in[0];   // [8,2048,384]
    const float* w_qkv  = (const float*)d_in[1];   // [384,1152]
    const float* w_proj = (const float*)d_in[2];   // [384,384]
    const float* b_proj = (const float*)d_in[3];   // [384]
    float* out = (float*)d_out;                    // [8,2048,384]

    cudaFuncSetAttribute(flash_attn_kernel,
                         cudaFuncAttributeMaxDynamicSharedMemorySize, 98304);

    {
        dim3 grid(C3 / 128, MROWS / 128);          // (9, 128)
        gemm_tf32_kernel<C3, false, 256, 128><<<grid, 256>>>(x, w_qkv, nullptr, nullptr);
    }
    {
        dim3 grid(TSEQ / 128, BATCH * NHEAD);      // (16, 48)
        flash_attn_kernel<<<grid, 256, 98304>>>();
    }
    {
        dim3 grid(CDIM / 128, MROWS / 64);         // (3, 256) = 768 blocks
        gemm_tf32_kernel<CDIM, true, 128, 64><<<grid, 128>>>(nullptr, w_proj, b_proj, out);
    }
}